// round 1
// baseline (speedup 1.0000x reference)
#include <cuda_runtime.h>
#include <cuda_bf16.h>
#include <math.h>

// Problem constants
#define B_   8
#define C_   256
#define IC_  128
#define H_   128
#define W_   128
#define H2_  64
#define W2_  64
#define NQ_  4096     // 64*64
#define NKV_ 1024     // 32*32

// ------------------------- scratch (device globals; no allocation) -------------------------
__device__ float d_rgb_p[B_ * C_ * NQ_];      // [B][C][4096]  32 MB
__device__ float d_ev_p [B_ * C_ * NQ_];      // [B][C][4096]  32 MB
__device__ float d_theta[B_ * NQ_ * IC_];     // [B][4096][128] 16 MB
__device__ float d_gconv[B_ * NQ_ * IC_];     // pre-pool g     16 MB
__device__ float d_pconv[B_ * NQ_ * IC_];     // pre-pool phi   16 MB
__device__ float d_g    [B_ * NKV_ * IC_];    // [B][1024][128]  4 MB
__device__ float d_phi  [B_ * NKV_ * IC_];    // [B][1024][128]  4 MB
__device__ float d_y    [B_ * NQ_ * IC_];     // [B][4096][128] 16 MB
__device__ float d_wy   [B_ * C_ * NQ_];      // [B][256][4096] 32 MB
__device__ float d_mean [C_];
__device__ float d_rstd [C_];

// ------------------------- 1) 2x2 maxpool NCHW, stride 2 -------------------------
__global__ void pool2_kernel(const float* __restrict__ in, float* __restrict__ out, int n) {
    int i = blockIdx.x * blockDim.x + threadIdx.x;
    if (i >= n) return;                      // n = B*C*64*64
    int ow = i & 63;
    int t  = i >> 6;
    int oh = t & 63;
    int bc = t >> 6;
    const float* p = in + ((size_t)bc * H_ + 2 * oh) * W_ + 2 * ow;
    float2 a = *(const float2*)p;
    float2 b = *(const float2*)(p + W_);
    out[i] = fmaxf(fmaxf(a.x, a.y), fmaxf(b.x, b.y));
}

// ------------------------- 2) 1x1 conv, input channel-major -------------------------
// x: [B][256][4096], w: [128][256], bias: [128] -> out: [B][4096][128]
// out[b][s][o] = sum_c x[b][c][s] * w[o][c] + bias[o]
__global__ void __launch_bounds__(256) conv_cmajor_kernel(
    const float* __restrict__ x, const float* __restrict__ w,
    const float* __restrict__ bias, float* __restrict__ out)
{
    __shared__ float Xs[32][64];   // [c][s]
    __shared__ float Ws[32][64];   // [c][o]
    int tid = threadIdx.x;
    int tx = tid & 15, ty = tid >> 4;        // frag: s rows via ty, o cols via tx
    int s0 = blockIdx.x * 64, o0 = blockIdx.y * 64, b = blockIdx.z;
    const float* xb = x + (size_t)b * C_ * NQ_;
    float acc[4][4] = {};                     // [si][oi]

    int ls = tid & 63, lc = tid >> 6;        // load indices
    for (int ct = 0; ct < C_ / 32; ++ct) {
        int c0 = ct * 32;
        __syncthreads();
        #pragma unroll
        for (int p = 0; p < 8; ++p)
            Xs[lc + p * 4][ls] = xb[(size_t)(c0 + lc + p * 4) * NQ_ + s0 + ls];
        #pragma unroll
        for (int p = 0; p < 8; ++p)
            Ws[lc + p * 4][ls] = w[(o0 + ls) * C_ + c0 + lc + p * 4];
        __syncthreads();
        #pragma unroll
        for (int c = 0; c < 32; ++c) {
            float4 xv = *(const float4*)&Xs[c][ty * 4];
            float4 wv = *(const float4*)&Ws[c][tx * 4];
            acc[0][0] += xv.x * wv.x; acc[0][1] += xv.x * wv.y; acc[0][2] += xv.x * wv.z; acc[0][3] += xv.x * wv.w;
            acc[1][0] += xv.y * wv.x; acc[1][1] += xv.y * wv.y; acc[1][2] += xv.y * wv.z; acc[1][3] += xv.y * wv.w;
            acc[2][0] += xv.z * wv.x; acc[2][1] += xv.z * wv.y; acc[2][2] += xv.z * wv.z; acc[2][3] += xv.z * wv.w;
            acc[3][0] += xv.w * wv.x; acc[3][1] += xv.w * wv.y; acc[3][2] += xv.w * wv.z; acc[3][3] += xv.w * wv.w;
        }
    }
    float4 bv = *(const float4*)&bias[o0 + tx * 4];
    #pragma unroll
    for (int si = 0; si < 4; ++si) {
        float4 r;
        r.x = acc[si][0] + bv.x; r.y = acc[si][1] + bv.y;
        r.z = acc[si][2] + bv.z; r.w = acc[si][3] + bv.w;
        *(float4*)&out[((size_t)b * NQ_ + s0 + ty * 4 + si) * IC_ + o0 + tx * 4] = r;
    }
}

// ------------------------- 3) row-pool [B][4096][128] -> [B][1024][128] -------------------------
__global__ void poolrows_kernel(const float* __restrict__ in, float* __restrict__ out, int n) {
    int i = blockIdx.x * blockDim.x + threadIdx.x;
    if (i >= n) return;                      // n = B*1024*32 (float4 units)
    int ic4 = i & 31;
    int kv  = (i >> 5) & 1023;
    int b   = i >> 15;
    int ph = kv >> 5, pw = kv & 31;
    int s00 = (ph * 2) * 64 + pw * 2;        // spatial (2ph, 2pw) in 64x64
    const float4* p = (const float4*)(in + ((size_t)b * NQ_ + s00) * IC_) + ic4;
    float4 a = p[0], c = p[32], d = p[64 * 32], e = p[65 * 32];
    float4 r;
    r.x = fmaxf(fmaxf(a.x, c.x), fmaxf(d.x, e.x));
    r.y = fmaxf(fmaxf(a.y, c.y), fmaxf(d.y, e.y));
    r.z = fmaxf(fmaxf(a.z, c.z), fmaxf(d.z, e.z));
    r.w = fmaxf(fmaxf(a.w, c.w), fmaxf(d.w, e.w));
    ((float4*)(out + ((size_t)b * NKV_ + kv) * IC_))[ic4] = r;
}

// ------------------------- 4) fused flash attention -------------------------
// Q = d_theta [B][4096][128], K = d_phi [B][1024][128], V = d_g [B][1024][128]
// y[b][q][:] = softmax_k( Q[q]·K[k] ) @ V    -> d_y [B][4096][128]
__global__ void __launch_bounds__(128) attn_kernel() {
    __shared__ float Qs [32][132];
    __shared__ float KGs[32][132];           // K tile, then reused as G tile
    __shared__ float Ss [32][36];            // scores / probs
    __shared__ float m_s[32], l_s[32], sc_s[32];

    int tid = threadIdx.x;
    int tx = tid & 15, ty = tid >> 4;        // 16 x 8
    int b = blockIdx.y;
    int q0 = blockIdx.x * 32;

    const float* Qg = d_theta + ((size_t)b * NQ_ + q0) * IC_;
    const float* Kg = d_phi + (size_t)b * NKV_ * IC_;
    const float* Gg = d_g   + (size_t)b * NKV_ * IC_;

    for (int i = tid; i < 32 * 128; i += 128) Qs[i >> 7][i & 127] = Qg[i];
    if (tid < 32) { m_s[tid] = -INFINITY; l_s[tid] = 0.f; }

    float O[4][8] = {};                      // [qi][ici]; q = ty*4+qi, ic = tx*8+ici

    for (int t = 0; t < NKV_ / 32; ++t) {
        __syncthreads();                     // prev GEMM2 done with KGs / Ss
        {
            const float* Kt = Kg + (size_t)t * 32 * IC_;
            for (int i = tid; i < 32 * 128; i += 128) KGs[i >> 7][i & 127] = Kt[i];
        }
        __syncthreads();

        // S = Q @ K^T  ; frag: q = ty*4+i, kv = j*16+tx
        float sf[4][2] = {};
        #pragma unroll
        for (int k = 0; k < 128; k += 4) {
            float4 qv0 = *(const float4*)&Qs[ty * 4 + 0][k];
            float4 qv1 = *(const float4*)&Qs[ty * 4 + 1][k];
            float4 qv2 = *(const float4*)&Qs[ty * 4 + 2][k];
            float4 qv3 = *(const float4*)&Qs[ty * 4 + 3][k];
            float4 kv0 = *(const float4*)&KGs[tx][k];
            float4 kv1 = *(const float4*)&KGs[16 + tx][k];
            sf[0][0] += qv0.x*kv0.x + qv0.y*kv0.y + qv0.z*kv0.z + qv0.w*kv0.w;
            sf[1][0] += qv1.x*kv0.x + qv1.y*kv0.y + qv1.z*kv0.z + qv1.w*kv0.w;
            sf[2][0] += qv2.x*kv0.x + qv2.y*kv0.y + qv2.z*kv0.z + qv2.w*kv0.w;
            sf[3][0] += qv3.x*kv0.x + qv3.y*kv0.y + qv3.z*kv0.z + qv3.w*kv0.w;
            sf[0][1] += qv0.x*kv1.x + qv0.y*kv1.y + qv0.z*kv1.z + qv0.w*kv1.w;
            sf[1][1] += qv1.x*kv1.x + qv1.y*kv1.y + qv1.z*kv1.z + qv1.w*kv1.w;
            sf[2][1] += qv2.x*kv1.x + qv2.y*kv1.y + qv2.z*kv1.z + qv2.w*kv1.w;
            sf[3][1] += qv3.x*kv1.x + qv3.y*kv1.y + qv3.z*kv1.z + qv3.w*kv1.w;
        }
        #pragma unroll
        for (int i = 0; i < 4; ++i) {
            Ss[ty * 4 + i][tx]      = sf[i][0];
            Ss[ty * 4 + i][16 + tx] = sf[i][1];
        }
        __syncthreads();

        // online softmax: row r handled by a 4-lane quad
        {
            int r = tid >> 2, lane = tid & 3;
            float mx = -INFINITY;
            #pragma unroll
            for (int c = 0; c < 8; ++c) mx = fmaxf(mx, Ss[r][lane * 8 + c]);
            mx = fmaxf(mx, __shfl_xor_sync(0xffffffffu, mx, 1));
            mx = fmaxf(mx, __shfl_xor_sync(0xffffffffu, mx, 2));
            float mold = m_s[r];
            float mnew = fmaxf(mold, mx);
            float scl  = __expf(mold - mnew);
            float ps = 0.f;
            #pragma unroll
            for (int c = 0; c < 8; ++c) {
                float p = __expf(Ss[r][lane * 8 + c] - mnew);
                Ss[r][lane * 8 + c] = p;
                ps += p;
            }
            ps += __shfl_xor_sync(0xffffffffu, ps, 1);
            ps += __shfl_xor_sync(0xffffffffu, ps, 2);
            if (lane == 0) { m_s[r] = mnew; l_s[r] = l_s[r] * scl + ps; sc_s[r] = scl; }
        }
        // load G tile into KGs (K reads finished before Ss barrier above)
        {
            const float* Gt = Gg + (size_t)t * 32 * IC_;
            for (int i = tid; i < 32 * 128; i += 128) KGs[i >> 7][i & 127] = Gt[i];
        }
        __syncthreads();

        // rescale accumulators, then O += P @ G
        #pragma unroll
        for (int i = 0; i < 4; ++i) {
            float s = sc_s[ty * 4 + i];
            #pragma unroll
            for (int j = 0; j < 8; ++j) O[i][j] *= s;
        }
        #pragma unroll 4
        for (int kv = 0; kv < 32; ++kv) {
            float4 g0 = *(const float4*)&KGs[kv][tx * 8];
            float4 g1 = *(const float4*)&KGs[kv][tx * 8 + 4];
            #pragma unroll
            for (int i = 0; i < 4; ++i) {
                float p = Ss[ty * 4 + i][kv];
                O[i][0] += p * g0.x; O[i][1] += p * g0.y; O[i][2] += p * g0.z; O[i][3] += p * g0.w;
                O[i][4] += p * g1.x; O[i][5] += p * g1.y; O[i][6] += p * g1.z; O[i][7] += p * g1.w;
            }
        }
    }

    float* yb = d_y + ((size_t)b * NQ_ + q0) * IC_;
    #pragma unroll
    for (int i = 0; i < 4; ++i) {
        float inv = 1.f / l_s[ty * 4 + i];
        float4 r0, r1;
        r0.x = O[i][0] * inv; r0.y = O[i][1] * inv; r0.z = O[i][2] * inv; r0.w = O[i][3] * inv;
        r1.x = O[i][4] * inv; r1.y = O[i][5] * inv; r1.z = O[i][6] * inv; r1.w = O[i][7] * inv;
        *(float4*)&yb[(size_t)(ty * 4 + i) * IC_ + tx * 8]     = r0;
        *(float4*)&yb[(size_t)(ty * 4 + i) * IC_ + tx * 8 + 4] = r1;
    }
}

// ------------------------- 5) output 1x1 conv: y [B][4096][128] -> wy [B][256][4096] -------------------------
// wy[b][co][s] = sum_ic y[b][s][ic] * W_w[co][ic] + W_b[co]
__global__ void __launch_bounds__(256) convW_kernel(
    const float* __restrict__ y, const float* __restrict__ w,
    const float* __restrict__ bias, float* __restrict__ out)
{
    __shared__ float Ys[32][68];   // [ic][s]
    __shared__ float Ws[32][68];   // [ic][co]
    int tid = threadIdx.x;
    int tx = tid & 15, ty = tid >> 4;        // frag: co rows via ty, s cols via tx
    int s0 = blockIdx.x * 64, co0 = blockIdx.y * 64, b = blockIdx.z;
    float acc[4][4] = {};                     // [ci][si]

    int lic = tid & 31, lr = tid >> 5;
    for (int kt = 0; kt < IC_ / 32; ++kt) {
        int ic0 = kt * 32;
        __syncthreads();
        #pragma unroll
        for (int p = 0; p < 8; ++p)
            Ys[lic][lr + p * 8] = y[((size_t)b * NQ_ + s0 + lr + p * 8) * IC_ + ic0 + lic];
        #pragma unroll
        for (int p = 0; p < 8; ++p)
            Ws[lic][lr + p * 8] = w[(co0 + lr + p * 8) * IC_ + ic0 + lic];
        __syncthreads();
        #pragma unroll
        for (int ic = 0; ic < 32; ++ic) {
            float4 sv = *(const float4*)&Ys[ic][tx * 4];
            float4 cv = *(const float4*)&Ws[ic][ty * 4];
            acc[0][0] += cv.x * sv.x; acc[0][1] += cv.x * sv.y; acc[0][2] += cv.x * sv.z; acc[0][3] += cv.x * sv.w;
            acc[1][0] += cv.y * sv.x; acc[1][1] += cv.y * sv.y; acc[1][2] += cv.y * sv.z; acc[1][3] += cv.y * sv.w;
            acc[2][0] += cv.z * sv.x; acc[2][1] += cv.z * sv.y; acc[2][2] += cv.z * sv.z; acc[2][3] += cv.z * sv.w;
            acc[3][0] += cv.w * sv.x; acc[3][1] += cv.w * sv.y; acc[3][2] += cv.w * sv.z; acc[3][3] += cv.w * sv.w;
        }
    }
    #pragma unroll
    for (int ci = 0; ci < 4; ++ci) {
        int co = co0 + ty * 4 + ci;
        float bb = bias[co];
        float4 r;
        r.x = acc[ci][0] + bb; r.y = acc[ci][1] + bb;
        r.z = acc[ci][2] + bb; r.w = acc[ci][3] + bb;
        *(float4*)&out[((size_t)b * C_ + co) * NQ_ + s0 + tx * 4] = r;
    }
}

// ------------------------- 6) BatchNorm stats (deterministic per-channel reduction) -------------------------
__global__ void bnstats_kernel() {
    __shared__ float ss[256], ss2[256];
    int co = blockIdx.x, tid = threadIdx.x;
    float s = 0.f, s2 = 0.f;
    for (int i = tid; i < B_ * NQ_; i += 256) {
        int b = i >> 12, sp = i & 4095;
        float v = d_wy[((size_t)b * C_ + co) * NQ_ + sp];
        s += v; s2 += v * v;
    }
    ss[tid] = s; ss2[tid] = s2;
    __syncthreads();
    for (int st = 128; st > 0; st >>= 1) {
        if (tid < st) { ss[tid] += ss[tid + st]; ss2[tid] += ss2[tid + st]; }
        __syncthreads();
    }
    if (tid == 0) {
        const float invN = 1.f / (B_ * NQ_);
        float mean = ss[0] * invN;
        float var  = ss2[0] * invN - mean * mean;
        d_mean[co] = mean;
        d_rstd[co] = rsqrtf(var + 1e-5f);
    }
}

// ------------------------- 7) BN apply + residual + 2x nearest upsample -------------------------
__global__ void final_kernel(const float* __restrict__ gamma, const float* __restrict__ beta,
                             float* __restrict__ out, int n) {
    int i = blockIdx.x * blockDim.x + threadIdx.x;
    if (i >= n) return;                      // n = B*C*128*128
    int w = i & 127;
    int t = i >> 7;
    int h = t & 127;
    t >>= 7;
    int co = t & 255;
    int b  = t >> 8;
    int s2 = (h >> 1) * W2_ + (w >> 1);
    size_t base = ((size_t)b * C_ + co) * NQ_ + s2;
    float v = (d_wy[base] - d_mean[co]) * d_rstd[co] * gamma[co] + beta[co] + d_rgb_p[base];
    out[i] = v;
}

// ------------------------- launch -------------------------
extern "C" void kernel_launch(void* const* d_in, const int* in_sizes, int n_in,
                              void* d_out, int out_size) {
    const float* rgb     = (const float*)d_in[0];
    const float* event_  = (const float*)d_in[1];
    const float* g_w     = (const float*)d_in[2];
    const float* g_b     = (const float*)d_in[3];
    const float* theta_w = (const float*)d_in[4];
    const float* theta_b = (const float*)d_in[5];
    const float* phi_w   = (const float*)d_in[6];
    const float* phi_b   = (const float*)d_in[7];
    const float* W_w     = (const float*)d_in[8];
    const float* W_b     = (const float*)d_in[9];
    const float* bn_g    = (const float*)d_in[10];
    const float* bn_b    = (const float*)d_in[11];
    float* out = (float*)d_out;

    float *rgb_p, *ev_p, *theta, *gconv, *pconv, *g, *phi, *y, *wy;
    cudaGetSymbolAddress((void**)&rgb_p, d_rgb_p);
    cudaGetSymbolAddress((void**)&ev_p,  d_ev_p);
    cudaGetSymbolAddress((void**)&theta, d_theta);
    cudaGetSymbolAddress((void**)&gconv, d_gconv);
    cudaGetSymbolAddress((void**)&pconv, d_pconv);
    cudaGetSymbolAddress((void**)&g,     d_g);
    cudaGetSymbolAddress((void**)&phi,   d_phi);
    cudaGetSymbolAddress((void**)&y,     d_y);
    cudaGetSymbolAddress((void**)&wy,    d_wy);

    // 1) initial 2x2 maxpool on both modalities
    {
        int n = B_ * C_ * H2_ * W2_;
        pool2_kernel<<<(n + 255) / 256, 256>>>(rgb,    rgb_p, n);
        pool2_kernel<<<(n + 255) / 256, 256>>>(event_, ev_p,  n);
    }
    // 2) 1x1 conv projections
    {
        dim3 grid(NQ_ / 64, IC_ / 64, B_);
        conv_cmajor_kernel<<<grid, 256>>>(rgb_p, theta_w, theta_b, theta);
        conv_cmajor_kernel<<<grid, 256>>>(ev_p,  g_w,     g_b,     gconv);
        conv_cmajor_kernel<<<grid, 256>>>(ev_p,  phi_w,   phi_b,   pconv);
    }
    // 3) sub-sample pool for g and phi
    {
        int n = B_ * NKV_ * (IC_ / 4);
        poolrows_kernel<<<(n + 255) / 256, 256>>>(gconv, g,   n);
        poolrows_kernel<<<(n + 255) / 256, 256>>>(pconv, phi, n);
    }
    // 4) fused attention
    {
        dim3 grid(NQ_ / 32, B_);
        attn_kernel<<<grid, 128>>>();
    }
    // 5) output 1x1 conv
    {
        dim3 grid(NQ_ / 64, C_ / 64, B_);
        convW_kernel<<<grid, 256>>>(y, W_w, W_b, wy);
    }
    // 6) BN stats
    bnstats_kernel<<<C_, 256>>>();
    // 7) BN apply + residual + 2x upsample
    {
        int n = B_ * C_ * H_ * W_;
        final_kernel<<<(n + 255) / 256, 256>>>(bn_g, bn_b, out, n);
    }
}

// round 4
// speedup vs baseline: 1.4860x; 1.4860x over previous
#include <cuda_runtime.h>
#include <math.h>

// Problem constants
#define B_   8
#define C_   256
#define IC_  128
#define H_   128
#define W_   128
#define H2_  64
#define W2_  64
#define NQ_  4096     // 64*64
#define NKV_ 1024     // 32*32

// ------------------------- scratch (device globals; no allocation) -------------------------
__device__ float d_rgb_p[B_ * C_ * NQ_];      // [B][C][4096]
__device__ float d_ev_p [B_ * C_ * NQ_];      // [B][C][4096]
__device__ float d_theta[B_ * NQ_ * IC_];     // [B][4096][128]
__device__ float d_gconv[B_ * NQ_ * IC_];     // pre-pool g
__device__ float d_pconv[B_ * NQ_ * IC_];     // pre-pool phi
__device__ float d_g    [B_ * NKV_ * IC_];    // [B][1024][128]
__device__ float d_phi  [B_ * NKV_ * IC_];    // [B][1024][128]
__device__ float d_S    [B_ * NQ_ * NKV_];    // [B][4096][1024] scores/probs
__device__ float d_y    [B_ * NQ_ * IC_];     // [B][4096][128]
__device__ float d_wy   [B_ * C_ * NQ_];      // [B][256][4096]
__device__ float d_mean [C_];
__device__ float d_rstd [C_];

// ------------------------- helpers: tf32 split + mma -------------------------
__device__ __forceinline__ float f2tf_f(float x) {
    unsigned u;
    asm("cvt.rna.tf32.f32 %0, %1;" : "=r"(u) : "f"(x));
    return __uint_as_float(u);
}
// hi = tf32(x), lo = tf32(x - hi)
__device__ __forceinline__ void split_tf(float x, float& hi, float& lo) {
    hi = f2tf_f(x);
    lo = f2tf_f(__fsub_rn(x, hi));
}

__device__ __forceinline__ void mma8(float* c, const unsigned* a, const unsigned* b) {
    asm volatile(
        "mma.sync.aligned.m16n8k8.row.col.f32.tf32.tf32.f32 "
        "{%0,%1,%2,%3}, {%4,%5,%6,%7}, {%8,%9}, {%0,%1,%2,%3};\n"
        : "+f"(c[0]), "+f"(c[1]), "+f"(c[2]), "+f"(c[3])
        : "r"(a[0]), "r"(a[1]), "r"(a[2]), "r"(a[3]), "r"(b[0]), "r"(b[1]));
}

// ------------------------- universal 3xTF32 tensor-core GEMM -------------------------
// C[m][n] = sum_k A(m,k) * B(k,n) (+bias), 128x128 block tile, ktile 16.
// Each operand split hi/lo; product = hi*hi + hi*lo + lo*hi (fp32-accurate).
// A_KMAJOR: A global layout [k][m]; else [m][k].  B_KMAJOR: [k][n]; else [n][k].
// BIAS_MODE: 0 none, 1 per-n, 2 per-m. M,N multiples of 128; K multiple of 16.
template<bool A_KMAJOR, bool B_KMAJOR, int BIAS_MODE>
__global__ void __launch_bounds__(256) gemm_tc(
    const float* __restrict__ A, const float* __restrict__ Bm,
    const float* __restrict__ bias, float* __restrict__ Cm,
    int K, int Astride, int Bstride, int Cstride,
    long sAb, long sBb, long sCb)
{
    __shared__ float Ash[16][136];
    __shared__ float Asl[16][136];
    __shared__ float Bsh[16][136];
    __shared__ float Bsl[16][136];
    int tid = threadIdx.x;
    int lane = tid & 31, warp = tid >> 5;
    int wm = warp >> 2, wn = warp & 3;           // 2 x 4 warp grid; warp tile 64m x 32n
    int m0 = blockIdx.x * 128, n0 = blockIdx.y * 128;
    int b = blockIdx.z;

    const float* Ag = A + (size_t)b * sAb;
    const float* Bg = Bm + (size_t)b * sBb;
    float* Cg = Cm + (size_t)b * sCb;
    if (A_KMAJOR) Ag += m0; else Ag += (size_t)m0 * Astride;
    if (B_KMAJOR) Bg += n0; else Bg += (size_t)n0 * Bstride;

    float acc[4][4][4] = {};                      // [mfrag][nfrag][4]

    for (int k0 = 0; k0 < K; k0 += 16) {
        __syncthreads();
        // ---- stage A tile into Ash/Asl [k][m] ----
        if (A_KMAJOR) {
            #pragma unroll
            for (int i = 0; i < 2; ++i) {
                int t = tid + i * 256;
                int k = t >> 5, m4 = (t & 31) << 2;
                float4 v = *(const float4*)&Ag[(size_t)(k0 + k) * Astride + m4];
                float4 h, l;
                split_tf(v.x, h.x, l.x); split_tf(v.y, h.y, l.y);
                split_tf(v.z, h.z, l.z); split_tf(v.w, h.w, l.w);
                *(float4*)&Ash[k][m4] = h;
                *(float4*)&Asl[k][m4] = l;
            }
        } else {
            #pragma unroll
            for (int i = 0; i < 2; ++i) {
                int t = tid + i * 256;
                int m = t & 127, k4 = (t >> 7) << 2;
                float4 v = *(const float4*)&Ag[(size_t)m * Astride + k0 + k4];
                float h, l;
                split_tf(v.x, h, l); Ash[k4 + 0][m] = h; Asl[k4 + 0][m] = l;
                split_tf(v.y, h, l); Ash[k4 + 1][m] = h; Asl[k4 + 1][m] = l;
                split_tf(v.z, h, l); Ash[k4 + 2][m] = h; Asl[k4 + 2][m] = l;
                split_tf(v.w, h, l); Ash[k4 + 3][m] = h; Asl[k4 + 3][m] = l;
            }
        }
        // ---- stage B tile into Bsh/Bsl [k][n] ----
        if (B_KMAJOR) {
            #pragma unroll
            for (int i = 0; i < 2; ++i) {
                int t = tid + i * 256;
                int k = t >> 5, n4 = (t & 31) << 2;
                float4 v = *(const float4*)&Bg[(size_t)(k0 + k) * Bstride + n4];
                float4 h, l;
                split_tf(v.x, h.x, l.x); split_tf(v.y, h.y, l.y);
                split_tf(v.z, h.z, l.z); split_tf(v.w, h.w, l.w);
                *(float4*)&Bsh[k][n4] = h;
                *(float4*)&Bsl[k][n4] = l;
            }
        } else {
            #pragma unroll
            for (int i = 0; i < 2; ++i) {
                int t = tid + i * 256;
                int n = t & 127, k4 = (t >> 7) << 2;
                float4 v = *(const float4*)&Bg[(size_t)n * Bstride + k0 + k4];
                float h, l;
                split_tf(v.x, h, l); Bsh[k4 + 0][n] = h; Bsl[k4 + 0][n] = l;
                split_tf(v.y, h, l); Bsh[k4 + 1][n] = h; Bsl[k4 + 1][n] = l;
                split_tf(v.z, h, l); Bsh[k4 + 2][n] = h; Bsl[k4 + 2][n] = l;
                split_tf(v.w, h, l); Bsh[k4 + 3][n] = h; Bsl[k4 + 3][n] = l;
            }
        }
        __syncthreads();

        // ---- 2 k-steps of m16n8k8, 3 mmas each (hh, hl, lh) ----
        #pragma unroll
        for (int ks = 0; ks < 16; ks += 8) {
            unsigned afh[4][4], afl[4][4], bfh[4][2], bfl[4][2];
            int kr = ks + (lane & 3);
            #pragma unroll
            for (int mi = 0; mi < 4; ++mi) {
                int mr = wm * 64 + mi * 16 + (lane >> 2);
                afh[mi][0] = __float_as_uint(Ash[kr][mr]);
                afh[mi][1] = __float_as_uint(Ash[kr][mr + 8]);
                afh[mi][2] = __float_as_uint(Ash[kr + 4][mr]);
                afh[mi][3] = __float_as_uint(Ash[kr + 4][mr + 8]);
                afl[mi][0] = __float_as_uint(Asl[kr][mr]);
                afl[mi][1] = __float_as_uint(Asl[kr][mr + 8]);
                afl[mi][2] = __float_as_uint(Asl[kr + 4][mr]);
                afl[mi][3] = __float_as_uint(Asl[kr + 4][mr + 8]);
            }
            #pragma unroll
            for (int ni = 0; ni < 4; ++ni) {
                int nc = wn * 32 + ni * 8 + (lane >> 2);
                bfh[ni][0] = __float_as_uint(Bsh[kr][nc]);
                bfh[ni][1] = __float_as_uint(Bsh[kr + 4][nc]);
                bfl[ni][0] = __float_as_uint(Bsl[kr][nc]);
                bfl[ni][1] = __float_as_uint(Bsl[kr + 4][nc]);
            }
            #pragma unroll
            for (int mi = 0; mi < 4; ++mi)
                #pragma unroll
                for (int ni = 0; ni < 4; ++ni) {
                    mma8(acc[mi][ni], afh[mi], bfl[ni]);   // hi*lo
                    mma8(acc[mi][ni], afl[mi], bfh[ni]);   // lo*hi
                    mma8(acc[mi][ni], afh[mi], bfh[ni]);   // hi*hi
                }
        }
    }

    // ---- epilogue: c-frag (row, 2*(lane&3)+{0,1}) float2 stores ----
    #pragma unroll
    for (int mi = 0; mi < 4; ++mi) {
        int r0 = m0 + wm * 64 + mi * 16 + (lane >> 2);
        #pragma unroll
        for (int ni = 0; ni < 4; ++ni) {
            int c0i = n0 + wn * 32 + ni * 8 + 2 * (lane & 3);
            float a0 = 0.f, a1 = 0.f, b0v = 0.f, b1v = 0.f;
            if (BIAS_MODE == 1) { a0 = bias[c0i]; a1 = bias[c0i + 1]; b0v = a0; b1v = a1; }
            if (BIAS_MODE == 2) { a0 = a1 = bias[r0]; b0v = b1v = bias[r0 + 8]; }
            float2 v0 = { acc[mi][ni][0] + a0, acc[mi][ni][1] + a1 };
            float2 v1 = { acc[mi][ni][2] + b0v, acc[mi][ni][3] + b1v };
            *(float2*)&Cg[(size_t)r0 * Cstride + c0i] = v0;
            *(float2*)&Cg[(size_t)(r0 + 8) * Cstride + c0i] = v1;
        }
    }
}

// ------------------------- 2x2 maxpool NCHW, stride 2 -------------------------
__global__ void pool2_kernel(const float* __restrict__ in, float* __restrict__ out, int n) {
    int i = blockIdx.x * blockDim.x + threadIdx.x;
    if (i >= n) return;
    int ow = i & 63;
    int t  = i >> 6;
    int oh = t & 63;
    int bc = t >> 6;
    const float* p = in + ((size_t)bc * H_ + 2 * oh) * W_ + 2 * ow;
    float2 a = *(const float2*)p;
    float2 b = *(const float2*)(p + W_);
    out[i] = fmaxf(fmaxf(a.x, a.y), fmaxf(b.x, b.y));
}

// ------------------------- row-pool [B][4096][128] -> [B][1024][128] -------------------------
__global__ void poolrows_kernel(const float* __restrict__ in, float* __restrict__ out, int n) {
    int i = blockIdx.x * blockDim.x + threadIdx.x;
    if (i >= n) return;                      // n = B*1024*32 (float4 units)
    int ic4 = i & 31;
    int kv  = (i >> 5) & 1023;
    int b   = i >> 15;
    int ph = kv >> 5, pw = kv & 31;
    int s00 = (ph * 2) * 64 + pw * 2;
    const float4* p = (const float4*)(in + ((size_t)b * NQ_ + s00) * IC_) + ic4;
    float4 a = p[0], c = p[32], d = p[64 * 32], e = p[65 * 32];
    float4 r;
    r.x = fmaxf(fmaxf(a.x, c.x), fmaxf(d.x, e.x));
    r.y = fmaxf(fmaxf(a.y, c.y), fmaxf(d.y, e.y));
    r.z = fmaxf(fmaxf(a.z, c.z), fmaxf(d.z, e.z));
    r.w = fmaxf(fmaxf(a.w, c.w), fmaxf(d.w, e.w));
    ((float4*)(out + ((size_t)b * NKV_ + kv) * IC_))[ic4] = r;
}

// ------------------------- warp-per-row softmax over 1024 -------------------------
__global__ void __launch_bounds__(256) softmax_kernel(float* __restrict__ S) {
    int warp = threadIdx.x >> 5, lane = threadIdx.x & 31;
    size_t row = (size_t)blockIdx.x * 8 + warp;
    float* p = S + row * NKV_ + lane * 4;
    float4 v[8];
    float mx = -INFINITY;
    #pragma unroll
    for (int j = 0; j < 8; ++j) {
        v[j] = *(const float4*)&p[j * 128];
        mx = fmaxf(mx, fmaxf(fmaxf(v[j].x, v[j].y), fmaxf(v[j].z, v[j].w)));
    }
    #pragma unroll
    for (int o = 16; o; o >>= 1) mx = fmaxf(mx, __shfl_xor_sync(0xffffffffu, mx, o));
    float s = 0.f;
    #pragma unroll
    for (int j = 0; j < 8; ++j) {
        v[j].x = __expf(v[j].x - mx);
        v[j].y = __expf(v[j].y - mx);
        v[j].z = __expf(v[j].z - mx);
        v[j].w = __expf(v[j].w - mx);
        s += (v[j].x + v[j].y) + (v[j].z + v[j].w);
    }
    #pragma unroll
    for (int o = 16; o; o >>= 1) s += __shfl_xor_sync(0xffffffffu, s, o);
    float inv = 1.f / s;
    #pragma unroll
    for (int j = 0; j < 8; ++j) {
        v[j].x *= inv; v[j].y *= inv; v[j].z *= inv; v[j].w *= inv;
        *(float4*)&p[j * 128] = v[j];
    }
}

// ------------------------- BatchNorm stats (deterministic) -------------------------
__global__ void bnstats_kernel() {
    __shared__ float ss[256], ss2[256];
    int co = blockIdx.x, tid = threadIdx.x;
    float s = 0.f, s2 = 0.f;
    for (int i = tid; i < B_ * NQ_; i += 256) {
        int b = i >> 12, sp = i & 4095;
        float v = d_wy[((size_t)b * C_ + co) * NQ_ + sp];
        s += v; s2 += v * v;
    }
    ss[tid] = s; ss2[tid] = s2;
    __syncthreads();
    for (int st = 128; st > 0; st >>= 1) {
        if (tid < st) { ss[tid] += ss[tid + st]; ss2[tid] += ss2[tid + st]; }
        __syncthreads();
    }
    if (tid == 0) {
        const float invN = 1.f / (B_ * NQ_);
        float mean = ss[0] * invN;
        float var  = ss2[0] * invN - mean * mean;
        d_mean[co] = mean;
        d_rstd[co] = rsqrtf(var + 1e-5f);
    }
}

// ------------------------- BN apply + residual + 2x nearest upsample -------------------------
__global__ void final_kernel(const float* __restrict__ gamma, const float* __restrict__ beta,
                             float* __restrict__ out, int n) {
    int i = blockIdx.x * blockDim.x + threadIdx.x;
    if (i >= n) return;
    int w = i & 127;
    int t = i >> 7;
    int h = t & 127;
    t >>= 7;
    int co = t & 255;
    int b  = t >> 8;
    int s2 = (h >> 1) * W2_ + (w >> 1);
    size_t base = ((size_t)b * C_ + co) * NQ_ + s2;
    float v = (d_wy[base] - d_mean[co]) * d_rstd[co] * gamma[co] + beta[co] + d_rgb_p[base];
    out[i] = v;
}

// ------------------------- launch -------------------------
extern "C" void kernel_launch(void* const* d_in, const int* in_sizes, int n_in,
                              void* d_out, int out_size) {
    const float* rgb     = (const float*)d_in[0];
    const float* event_  = (const float*)d_in[1];
    const float* g_w     = (const float*)d_in[2];
    const float* g_b     = (const float*)d_in[3];
    const float* theta_w = (const float*)d_in[4];
    const float* theta_b = (const float*)d_in[5];
    const float* phi_w   = (const float*)d_in[6];
    const float* phi_b   = (const float*)d_in[7];
    const float* W_w     = (const float*)d_in[8];
    const float* W_b     = (const float*)d_in[9];
    const float* bn_g    = (const float*)d_in[10];
    const float* bn_b    = (const float*)d_in[11];
    float* out = (float*)d_out;

    float *rgb_p, *ev_p, *theta, *gconv, *pconv, *g, *phi, *S, *y, *wy;
    cudaGetSymbolAddress((void**)&rgb_p, d_rgb_p);
    cudaGetSymbolAddress((void**)&ev_p,  d_ev_p);
    cudaGetSymbolAddress((void**)&theta, d_theta);
    cudaGetSymbolAddress((void**)&gconv, d_gconv);
    cudaGetSymbolAddress((void**)&pconv, d_pconv);
    cudaGetSymbolAddress((void**)&g,     d_g);
    cudaGetSymbolAddress((void**)&phi,   d_phi);
    cudaGetSymbolAddress((void**)&S,     d_S);
    cudaGetSymbolAddress((void**)&y,     d_y);
    cudaGetSymbolAddress((void**)&wy,    d_wy);

    // 1) initial 2x2 maxpool on both modalities
    {
        int n = B_ * C_ * H2_ * W2_;
        pool2_kernel<<<(n + 255) / 256, 256>>>(rgb,    rgb_p, n);
        pool2_kernel<<<(n + 255) / 256, 256>>>(event_, ev_p,  n);
    }
    // 2) 1x1 conv projections: out[b][s][o] = sum_c x[b][c][s] w[o][c] + b[o]
    //    A = x (k-major, Astride=4096), B = w (n-major, Bstride=256), bias per-n
    {
        dim3 grid(NQ_ / 128, 1, B_);
        gemm_tc<true, false, 1><<<grid, 256>>>(rgb_p, theta_w, theta_b, theta,
            C_, NQ_, C_, IC_, (long)C_ * NQ_, 0, (long)NQ_ * IC_);
        gemm_tc<true, false, 1><<<grid, 256>>>(ev_p, g_w, g_b, gconv,
            C_, NQ_, C_, IC_, (long)C_ * NQ_, 0, (long)NQ_ * IC_);
        gemm_tc<true, false, 1><<<grid, 256>>>(ev_p, phi_w, phi_b, pconv,
            C_, NQ_, C_, IC_, (long)C_ * NQ_, 0, (long)NQ_ * IC_);
    }
    // 3) sub-sample pool for g and phi
    {
        int n = B_ * NKV_ * (IC_ / 4);
        poolrows_kernel<<<(n + 255) / 256, 256>>>(gconv, g,   n);
        poolrows_kernel<<<(n + 255) / 256, 256>>>(pconv, phi, n);
    }
    // 4a) scores: S[b][q][kv] = sum_c theta[b][q][c] phi[b][kv][c]
    //     A = theta (m-major, Astride=128), B = phi (n-major, Bstride=128)
    {
        dim3 grid(NQ_ / 128, NKV_ / 128, B_);
        gemm_tc<false, false, 0><<<grid, 256>>>(theta, phi, nullptr, S,
            IC_, IC_, IC_, NKV_, (long)NQ_ * IC_, (long)NKV_ * IC_, (long)NQ_ * NKV_);
    }
    // 4b) softmax rows
    softmax_kernel<<<B_ * NQ_ / 8, 256>>>(S);
    // 4c) y[b][q][ic] = sum_kv P[b][q][kv] g[b][kv][ic]
    //     A = P (m-major, Astride=1024), B = g (k-major, Bstride=128)
    {
        dim3 grid(NQ_ / 128, 1, B_);
        gemm_tc<false, true, 0><<<grid, 256>>>(S, g, nullptr, y,
            NKV_, NKV_, IC_, IC_, (long)NQ_ * NKV_, (long)NKV_ * IC_, (long)NQ_ * IC_);
    }
    // 5) output conv: wy[b][co][s] = sum_ic W_w[co][ic] y[b][s][ic] + W_b[co]
    //    A = W_w (m-major, Astride=128, shared), B = y (n-major, Bstride=128), bias per-m
    {
        dim3 grid(C_ / 128, NQ_ / 128, B_);
        gemm_tc<false, false, 2><<<grid, 256>>>(W_w, y, W_b, wy,
            IC_, IC_, IC_, NQ_, 0, (long)NQ_ * IC_, (long)C_ * NQ_);
    }
    // 6) BN stats
    bnstats_kernel<<<C_, 256>>>();
    // 7) BN apply + residual + 2x upsample
    {
        int n = B_ * C_ * H_ * W_;
        final_kernel<<<(n + 255) / 256, 256>>>(bn_g, bn_b, out, n);
    }
}

// round 8
// speedup vs baseline: 1.9638x; 1.3215x over previous
#include <cuda_runtime.h>
#include <math.h>

// Problem constants
#define B_   8
#define C_   256
#define IC_  128
#define H_   128
#define W_   128
#define H2_  64
#define W2_  64
#define NQ_  4096     // 64*64
#define NKV_ 1024     // 32*32

// ------------------------- scratch (device globals; no allocation) -------------------------
__device__ float d_rgb_p[B_ * C_ * NQ_];      // [B][C][4096]
__device__ float d_ev_p [B_ * C_ * NQ_];      // [B][C][4096]
__device__ float d_theta[B_ * NQ_ * IC_];     // [B][4096][128]
__device__ float d_gconv[B_ * NQ_ * IC_];     // pre-pool g
__device__ float d_pconv[B_ * NQ_ * IC_];     // pre-pool phi
__device__ float d_g    [B_ * NKV_ * IC_];    // [B][1024][128]
__device__ float d_phi  [B_ * NKV_ * IC_];    // [B][1024][128]
__device__ float d_S    [B_ * NQ_ * NKV_];    // [B][4096][1024] scores/probs
__device__ float d_y    [B_ * NQ_ * IC_];     // [B][4096][128]
__device__ float d_wy   [B_ * C_ * NQ_];      // [B][256][4096]
__device__ float d_mean [C_];
__device__ float d_rstd [C_];

// ------------------------- helpers -------------------------
__device__ __forceinline__ float f2tf_f(float x) {
    unsigned u;
    asm("cvt.rna.tf32.f32 %0, %1;" : "=r"(u) : "f"(x));
    return __uint_as_float(u);
}

__device__ __forceinline__ void mma8(float* c, const unsigned* a, const unsigned* b) {
    asm volatile(
        "mma.sync.aligned.m16n8k8.row.col.f32.tf32.tf32.f32 "
        "{%0,%1,%2,%3}, {%4,%5,%6,%7}, {%8,%9}, {%0,%1,%2,%3};\n"
        : "+f"(c[0]), "+f"(c[1]), "+f"(c[2]), "+f"(c[3])
        : "r"(a[0]), "r"(a[1]), "r"(a[2]), "r"(a[3]), "r"(b[0]), "r"(b[1]));
}

__device__ __forceinline__ void cpa16(void* s, const void* g) {
    unsigned ss = (unsigned)__cvta_generic_to_shared(s);
    asm volatile("cp.async.cg.shared.global [%0], [%1], 16;\n" :: "r"(ss), "l"(g));
}
#define CP_COMMIT() asm volatile("cp.async.commit_group;\n")
#define CP_WAIT0()  asm volatile("cp.async.wait_group 0;\n" ::: "memory")

// Natural-layout double-buffered smem tiles.
// k-major: [k=16][val 128 pad 136]  (stride 136 % 32 = 8 -> frag loads conflict-free)
// m-major: [m/n=128][k=16 pad 20]   (stride 20: bases {0,20,8,28,16,4,24,12}+k -> conflict-free)
template<bool KMAJ> struct Tile;
template<> struct Tile<true>  { float d[2][16][136]; };
template<> struct Tile<false> { float d[2][128][20]; };

// ------------------------- 3xTF32 GEMM body -------------------------
// C[m][n] = sum_k A(m,k)*B(k,n) (+bias). 128x128 block tile, ktile 16, cp.async 2-stage.
// hi = tf32(v), lo = v-hi (raw; tensor HW truncates). product = lo*hi + hi*lo + hi*hi.
template<bool A_KMAJOR, bool B_KMAJOR, int BIAS_MODE>
__device__ __forceinline__ void gemm_body(
    const float* __restrict__ Ag, const float* __restrict__ Bg,
    const float* __restrict__ bias, float* __restrict__ Cg,
    int K, int Astride, int Bstride, int Cstride, int m0, int n0,
    Tile<A_KMAJOR>& As, Tile<B_KMAJOR>& Bs)
{
    int tid = threadIdx.x;
    int lane = tid & 31, warp = tid >> 5;
    int wm = warp >> 2, wn = warp & 3;           // 2 x 4 warps; warp tile 64m x 32n
    float acc[4][4][4] = {};
    int nkt = K / 16;

    auto stage = [&](int kt, int bf) {
        if constexpr (A_KMAJOR) {
            #pragma unroll
            for (int i = 0; i < 2; ++i) {
                int o = tid + i * 256;
                int r = o >> 5, c = (o & 31) << 2;
                cpa16(&As.d[bf][r][c], &Ag[(size_t)(kt * 16 + r) * Astride + c]);
            }
        } else {
            #pragma unroll
            for (int i = 0; i < 2; ++i) {
                int o = tid + i * 256;
                int r = o >> 2, c = (o & 3) << 2;
                cpa16(&As.d[bf][r][c], &Ag[(size_t)r * Astride + kt * 16 + c]);
            }
        }
        if constexpr (B_KMAJOR) {
            #pragma unroll
            for (int i = 0; i < 2; ++i) {
                int o = tid + i * 256;
                int r = o >> 5, c = (o & 31) << 2;
                cpa16(&Bs.d[bf][r][c], &Bg[(size_t)(kt * 16 + r) * Bstride + c]);
            }
        } else {
            #pragma unroll
            for (int i = 0; i < 2; ++i) {
                int o = tid + i * 256;
                int r = o >> 2, c = (o & 3) << 2;
                cpa16(&Bs.d[bf][r][c], &Bg[(size_t)r * Bstride + kt * 16 + c]);
            }
        }
    };

    stage(0, 0);
    CP_COMMIT();
    CP_WAIT0();
    __syncthreads();

    for (int kt = 0; kt < nkt; ++kt) {
        int cur = kt & 1;
        if (kt + 1 < nkt) stage(kt + 1, cur ^ 1);
        CP_COMMIT();

        #pragma unroll
        for (int ks = 0; ks < 16; ks += 8) {
            int kr = ks + (lane & 3);
            unsigned afh[4][4], afl[4][4], bfh[4][2], bfl[4][2];
            #pragma unroll
            for (int mi = 0; mi < 4; ++mi) {
                int mr = wm * 64 + mi * 16 + (lane >> 2);
                float v0, v1, v2, v3;
                if constexpr (A_KMAJOR) {
                    v0 = As.d[cur][kr][mr];     v1 = As.d[cur][kr][mr + 8];
                    v2 = As.d[cur][kr + 4][mr]; v3 = As.d[cur][kr + 4][mr + 8];
                } else {
                    v0 = As.d[cur][mr][kr];     v1 = As.d[cur][mr + 8][kr];
                    v2 = As.d[cur][mr][kr + 4]; v3 = As.d[cur][mr + 8][kr + 4];
                }
                float h;
                h = f2tf_f(v0); afh[mi][0] = __float_as_uint(h); afl[mi][0] = __float_as_uint(v0 - h);
                h = f2tf_f(v1); afh[mi][1] = __float_as_uint(h); afl[mi][1] = __float_as_uint(v1 - h);
                h = f2tf_f(v2); afh[mi][2] = __float_as_uint(h); afl[mi][2] = __float_as_uint(v2 - h);
                h = f2tf_f(v3); afh[mi][3] = __float_as_uint(h); afl[mi][3] = __float_as_uint(v3 - h);
            }
            #pragma unroll
            for (int ni = 0; ni < 4; ++ni) {
                int nc = wn * 32 + ni * 8 + (lane >> 2);
                float v0, v1;
                if constexpr (B_KMAJOR) {
                    v0 = Bs.d[cur][kr][nc]; v1 = Bs.d[cur][kr + 4][nc];
                } else {
                    v0 = Bs.d[cur][nc][kr]; v1 = Bs.d[cur][nc][kr + 4];
                }
                float h;
                h = f2tf_f(v0); bfh[ni][0] = __float_as_uint(h); bfl[ni][0] = __float_as_uint(v0 - h);
                h = f2tf_f(v1); bfh[ni][1] = __float_as_uint(h); bfl[ni][1] = __float_as_uint(v1 - h);
            }
            #pragma unroll
            for (int mi = 0; mi < 4; ++mi)
                #pragma unroll
                for (int ni = 0; ni < 4; ++ni) {
                    mma8(acc[mi][ni], afl[mi], bfh[ni]);   // lo*hi
                    mma8(acc[mi][ni], afh[mi], bfl[ni]);   // hi*lo
                    mma8(acc[mi][ni], afh[mi], bfh[ni]);   // hi*hi
                }
        }

        CP_WAIT0();
        __syncthreads();
    }

    // ---- epilogue ----
    #pragma unroll
    for (int mi = 0; mi < 4; ++mi) {
        int r0 = m0 + wm * 64 + mi * 16 + (lane >> 2);
        #pragma unroll
        for (int ni = 0; ni < 4; ++ni) {
            int c0i = n0 + wn * 32 + ni * 8 + 2 * (lane & 3);
            float a0 = 0.f, a1 = 0.f, b0v = 0.f, b1v = 0.f;
            if (BIAS_MODE == 1) { a0 = bias[c0i]; a1 = bias[c0i + 1]; b0v = a0; b1v = a1; }
            if (BIAS_MODE == 2) { a0 = a1 = bias[r0]; b0v = b1v = bias[r0 + 8]; }
            float2 v0 = { acc[mi][ni][0] + a0, acc[mi][ni][1] + a1 };
            float2 v1 = { acc[mi][ni][2] + b0v, acc[mi][ni][3] + b1v };
            *(float2*)&Cg[(size_t)r0 * Cstride + c0i] = v0;
            *(float2*)&Cg[(size_t)(r0 + 8) * Cstride + c0i] = v1;
        }
    }
}

// ------------------------- generic GEMM kernel -------------------------
template<bool A_KMAJOR, bool B_KMAJOR, int BIAS_MODE>
__global__ void __launch_bounds__(256) gemm_tc(
    const float* __restrict__ A, const float* __restrict__ Bm,
    const float* __restrict__ bias, float* __restrict__ Cm,
    int K, int Astride, int Bstride, int Cstride,
    long sAb, long sBb, long sCb)
{
    __shared__ Tile<A_KMAJOR> As;
    __shared__ Tile<B_KMAJOR> Bs;
    int m0 = blockIdx.x * 128, n0 = blockIdx.y * 128;
    int b = blockIdx.z;
    const float* Ag = A + (size_t)b * sAb;
    const float* Bg = Bm + (size_t)b * sBb;
    float* Cg = Cm + (size_t)b * sCb;
    if (A_KMAJOR) Ag += m0; else Ag += (size_t)m0 * Astride;
    if (B_KMAJOR) Bg += n0; else Bg += (size_t)n0 * Bstride;
    gemm_body<A_KMAJOR, B_KMAJOR, BIAS_MODE>(
        Ag, Bg, bias, Cg, K, Astride, Bstride, Cstride, m0, n0, As, Bs);
}

// ------------------------- merged projection kernel (3 GEMMs, one launch) -------------------------
// z = proj*8 + b; proj 0: theta(rgb_p), 1: g(ev_p), 2: phi(ev_p)
__global__ void __launch_bounds__(256) gemm_proj(
    const float* __restrict__ rgb_p, const float* __restrict__ ev_p,
    const float* __restrict__ tw, const float* __restrict__ tb,
    const float* __restrict__ gw, const float* __restrict__ gb,
    const float* __restrict__ pw, const float* __restrict__ pb,
    float* __restrict__ theta, float* __restrict__ gconv, float* __restrict__ pconv)
{
    __shared__ Tile<true> As;
    __shared__ Tile<false> Bs;
    int z = blockIdx.z;
    int pz = z >> 3, b = z & 7;
    const float* Aall = (pz == 0) ? rgb_p : ev_p;
    const float* Bw   = (pz == 0) ? tw : (pz == 1 ? gw : pw);
    const float* bias = (pz == 0) ? tb : (pz == 1 ? gb : pb);
    float* Cm         = (pz == 0) ? theta : (pz == 1 ? gconv : pconv);
    int m0 = blockIdx.x * 128;
    const float* Ag = Aall + (size_t)b * C_ * NQ_ + m0;   // k-major [256][4096]
    float* Cg = Cm + (size_t)b * NQ_ * IC_;
    gemm_body<true, false, 1>(Ag, Bw, bias, Cg, C_, NQ_, C_, IC_, m0, 0, As, Bs);
}

// ------------------------- 2x2 maxpool NCHW, stride 2 -------------------------
__global__ void pool2_kernel(const float* __restrict__ in, float* __restrict__ out, int n) {
    int i = blockIdx.x * blockDim.x + threadIdx.x;
    if (i >= n) return;
    int ow = i & 63;
    int t  = i >> 6;
    int oh = t & 63;
    int bc = t >> 6;
    const float* p = in + ((size_t)bc * H_ + 2 * oh) * W_ + 2 * ow;
    float2 a = *(const float2*)p;
    float2 b = *(const float2*)(p + W_);
    out[i] = fmaxf(fmaxf(a.x, a.y), fmaxf(b.x, b.y));
}

// ------------------------- row-pool [B][4096][128] -> [B][1024][128] -------------------------
__global__ void poolrows_kernel(const float* __restrict__ in, float* __restrict__ out, int n) {
    int i = blockIdx.x * blockDim.x + threadIdx.x;
    if (i >= n) return;                      // n = B*1024*32 (float4 units)
    int ic4 = i & 31;
    int kv  = (i >> 5) & 1023;
    int b   = i >> 15;
    int ph = kv >> 5, pw = kv & 31;
    int s00 = (ph * 2) * 64 + pw * 2;
    const float4* p = (const float4*)(in + ((size_t)b * NQ_ + s00) * IC_) + ic4;
    float4 a = p[0], c = p[32], d = p[64 * 32], e = p[65 * 32];
    float4 r;
    r.x = fmaxf(fmaxf(a.x, c.x), fmaxf(d.x, e.x));
    r.y = fmaxf(fmaxf(a.y, c.y), fmaxf(d.y, e.y));
    r.z = fmaxf(fmaxf(a.z, c.z), fmaxf(d.z, e.z));
    r.w = fmaxf(fmaxf(a.w, c.w), fmaxf(d.w, e.w));
    ((float4*)(out + ((size_t)b * NKV_ + kv) * IC_))[ic4] = r;
}

// ------------------------- warp-per-row softmax over 1024 -------------------------
__global__ void __launch_bounds__(256) softmax_kernel(float* __restrict__ S) {
    int warp = threadIdx.x >> 5, lane = threadIdx.x & 31;
    size_t row = (size_t)blockIdx.x * 8 + warp;
    float* p = S + row * NKV_ + lane * 4;
    float4 v[8];
    float mx = -INFINITY;
    #pragma unroll
    for (int j = 0; j < 8; ++j) {
        v[j] = *(const float4*)&p[j * 128];
        mx = fmaxf(mx, fmaxf(fmaxf(v[j].x, v[j].y), fmaxf(v[j].z, v[j].w)));
    }
    #pragma unroll
    for (int o = 16; o; o >>= 1) mx = fmaxf(mx, __shfl_xor_sync(0xffffffffu, mx, o));
    float s = 0.f;
    #pragma unroll
    for (int j = 0; j < 8; ++j) {
        v[j].x = __expf(v[j].x - mx);
        v[j].y = __expf(v[j].y - mx);
        v[j].z = __expf(v[j].z - mx);
        v[j].w = __expf(v[j].w - mx);
        s += (v[j].x + v[j].y) + (v[j].z + v[j].w);
    }
    #pragma unroll
    for (int o = 16; o; o >>= 1) s += __shfl_xor_sync(0xffffffffu, s, o);
    float inv = 1.f / s;
    #pragma unroll
    for (int j = 0; j < 8; ++j) {
        v[j].x *= inv; v[j].y *= inv; v[j].z *= inv; v[j].w *= inv;
        *(float4*)&p[j * 128] = v[j];
    }
}

// ------------------------- BatchNorm stats (deterministic) -------------------------
__global__ void bnstats_kernel() {
    __shared__ float ss[256], ss2[256];
    int co = blockIdx.x, tid = threadIdx.x;
    float s = 0.f, s2 = 0.f;
    for (int i = tid; i < B_ * NQ_; i += 256) {
        int b = i >> 12, sp = i & 4095;
        float v = d_wy[((size_t)b * C_ + co) * NQ_ + sp];
        s += v; s2 += v * v;
    }
    ss[tid] = s; ss2[tid] = s2;
    __syncthreads();
    for (int st = 128; st > 0; st >>= 1) {
        if (tid < st) { ss[tid] += ss[tid + st]; ss2[tid] += ss2[tid + st]; }
        __syncthreads();
    }
    if (tid == 0) {
        const float invN = 1.f / (B_ * NQ_);
        float mean = ss[0] * invN;
        float var  = ss2[0] * invN - mean * mean;
        d_mean[co] = mean;
        d_rstd[co] = rsqrtf(var + 1e-5f);
    }
}

// ------------------------- BN apply + residual + 2x nearest upsample -------------------------
__global__ void final_kernel(const float* __restrict__ gamma, const float* __restrict__ beta,
                             float* __restrict__ out, int n) {
    int i = blockIdx.x * blockDim.x + threadIdx.x;
    if (i >= n) return;
    int w = i & 127;
    int t = i >> 7;
    int h = t & 127;
    t >>= 7;
    int co = t & 255;
    int b  = t >> 8;
    int s2 = (h >> 1) * W2_ + (w >> 1);
    size_t base = ((size_t)b * C_ + co) * NQ_ + s2;
    float v = (d_wy[base] - d_mean[co]) * d_rstd[co] * gamma[co] + beta[co] + d_rgb_p[base];
    out[i] = v;
}

// ------------------------- launch -------------------------
extern "C" void kernel_launch(void* const* d_in, const int* in_sizes, int n_in,
                              void* d_out, int out_size) {
    const float* rgb     = (const float*)d_in[0];
    const float* event_  = (const float*)d_in[1];
    const float* g_w     = (const float*)d_in[2];
    const float* g_b     = (const float*)d_in[3];
    const float* theta_w = (const float*)d_in[4];
    const float* theta_b = (const float*)d_in[5];
    const float* phi_w   = (const float*)d_in[6];
    const float* phi_b   = (const float*)d_in[7];
    const float* W_w     = (const float*)d_in[8];
    const float* W_b     = (const float*)d_in[9];
    const float* bn_g    = (const float*)d_in[10];
    const float* bn_b    = (const float*)d_in[11];
    float* out = (float*)d_out;

    float *rgb_p, *ev_p, *theta, *gconv, *pconv, *g, *phi, *S, *y, *wy;
    cudaGetSymbolAddress((void**)&rgb_p, d_rgb_p);
    cudaGetSymbolAddress((void**)&ev_p,  d_ev_p);
    cudaGetSymbolAddress((void**)&theta, d_theta);
    cudaGetSymbolAddress((void**)&gconv, d_gconv);
    cudaGetSymbolAddress((void**)&pconv, d_pconv);
    cudaGetSymbolAddress((void**)&g,     d_g);
    cudaGetSymbolAddress((void**)&phi,   d_phi);
    cudaGetSymbolAddress((void**)&S,     d_S);
    cudaGetSymbolAddress((void**)&y,     d_y);
    cudaGetSymbolAddress((void**)&wy,    d_wy);

    // 1) initial 2x2 maxpool on both modalities
    {
        int n = B_ * C_ * H2_ * W2_;
        pool2_kernel<<<(n + 255) / 256, 256>>>(rgb,    rgb_p, n);
        pool2_kernel<<<(n + 255) / 256, 256>>>(event_, ev_p,  n);
    }
    // 2) merged 1x1 conv projections (theta, g, phi) in one launch
    {
        dim3 grid(NQ_ / 128, 1, 24);
        gemm_proj<<<grid, 256>>>(rgb_p, ev_p, theta_w, theta_b, g_w, g_b,
                                 phi_w, phi_b, theta, gconv, pconv);
    }
    // 3) sub-sample pool for g and phi
    {
        int n = B_ * NKV_ * (IC_ / 4);
        poolrows_kernel<<<(n + 255) / 256, 256>>>(gconv, g,   n);
        poolrows_kernel<<<(n + 255) / 256, 256>>>(pconv, phi, n);
    }
    // 4a) scores: S[b][q][kv] = sum_c theta[b][q][c] phi[b][kv][c]
    {
        dim3 grid(NQ_ / 128, NKV_ / 128, B_);
        gemm_tc<false, false, 0><<<grid, 256>>>(theta, phi, nullptr, S,
            IC_, IC_, IC_, NKV_, (long)NQ_ * IC_, (long)NKV_ * IC_, (long)NQ_ * NKV_);
    }
    // 4b) softmax rows
    softmax_kernel<<<B_ * NQ_ / 8, 256>>>(S);
    // 4c) y[b][q][ic] = sum_kv P[b][q][kv] g[b][kv][ic]
    {
        dim3 grid(NQ_ / 128, 1, B_);
        gemm_tc<false, true, 0><<<grid, 256>>>(S, g, nullptr, y,
            NKV_, NKV_, IC_, IC_, (long)NQ_ * NKV_, (long)NKV_ * IC_, (long)NQ_ * IC_);
    }
    // 5) output conv: wy[b][co][s] = sum_ic W_w[co][ic] y[b][s][ic] + W_b[co]
    {
        dim3 grid(C_ / 128, NQ_ / 128, B_);
        gemm_tc<false, false, 2><<<grid, 256>>>(W_w, y, W_b, wy,
            IC_, IC_, IC_, NQ_, 0, (long)NQ_ * IC_, (long)C_ * NQ_);
    }
    // 6) BN stats
    bnstats_kernel<<<C_, 256>>>();
    // 7) BN apply + residual + 2x upsample
    {
        int n = B_ * C_ * H_ * W_;
        final_kernel<<<(n + 255) / 256, 256>>>(bn_g, bn_b, out, n);
    }
}

// round 12
// speedup vs baseline: 2.2309x; 1.1360x over previous
#include <cuda_runtime.h>
#include <math.h>

// Problem constants
#define B_   8
#define C_   256
#define IC_  128
#define H_   128
#define W_   128
#define H2_  64
#define W2_  64
#define NQ_  4096     // 64*64
#define NKV_ 1024     // 32*32

// ------------------------- scratch (device globals; no allocation) -------------------------
__device__ float d_rgb_p[B_ * C_ * NQ_];      // [B][C][4096]
__device__ float d_ev_p [B_ * C_ * NQ_];      // [B][C][4096]
__device__ float d_theta[B_ * NQ_ * IC_];     // [B][4096][128]
__device__ float d_gconv[B_ * NQ_ * IC_];     // pre-pool g
__device__ float d_pconv[B_ * NQ_ * IC_];     // pre-pool phi
__device__ float d_g    [B_ * NKV_ * IC_];    // [B][1024][128]
__device__ float d_phi  [B_ * NKV_ * IC_];    // [B][1024][128]
__device__ float d_S    [B_ * NQ_ * NKV_];    // [B][4096][1024] scores/probs
__device__ float d_y    [B_ * NQ_ * IC_];     // [B][4096][128]
__device__ float d_wy   [B_ * C_ * NQ_];      // [B][256][4096]
__device__ float d_mean [C_];
__device__ float d_rstd [C_];

// ------------------------- helpers -------------------------
__device__ __forceinline__ float f2tf_f(float x) {
    unsigned u;
    asm("cvt.rna.tf32.f32 %0, %1;" : "=r"(u) : "f"(x));
    return __uint_as_float(u);
}
__device__ __forceinline__ unsigned fu(float x) { return __float_as_uint(x); }

__device__ __forceinline__ void mma8(float* c, const unsigned* a, const unsigned* b) {
    asm volatile(
        "mma.sync.aligned.m16n8k8.row.col.f32.tf32.tf32.f32 "
        "{%0,%1,%2,%3}, {%4,%5,%6,%7}, {%8,%9}, {%0,%1,%2,%3};\n"
        : "+f"(c[0]), "+f"(c[1]), "+f"(c[2]), "+f"(c[3])
        : "r"(a[0]), "r"(a[1]), "r"(a[2]), "r"(a[3]), "r"(b[0]), "r"(b[1]));
}

__device__ __forceinline__ void cpa16(void* s, const void* g) {
    unsigned ss = (unsigned)__cvta_generic_to_shared(s);
    asm volatile("cp.async.cg.shared.global [%0], [%1], 16;\n" :: "r"(ss), "l"(g));
}
#define CP_COMMIT() asm volatile("cp.async.commit_group;\n")
#define CP_WAIT0()  asm volatile("cp.async.wait_group 0;\n" ::: "memory")

// ------------------------- generic GEMM infrastructure -------------------------
template<bool KMAJ> struct Tile;
template<> struct Tile<true>  { float d[2][16][136]; };
template<> struct Tile<false> { float d[2][128][20]; };

template<bool A_KMAJOR, bool B_KMAJOR, int BIAS_MODE>
__device__ __forceinline__ void gemm_body(
    const float* __restrict__ Ag, const float* __restrict__ Bg,
    const float* __restrict__ bias, float* __restrict__ Cg,
    int K, int Astride, int Bstride, int Cstride, int m0, int n0,
    Tile<A_KMAJOR>& As, Tile<B_KMAJOR>& Bs)
{
    int tid = threadIdx.x;
    int lane = tid & 31, warp = tid >> 5;
    int wm = warp >> 2, wn = warp & 3;           // 2 x 4 warps; warp tile 64m x 32n
    float acc[4][4][4] = {};
    int nkt = K / 16;

    auto stage = [&](int kt, int bf) {
        if constexpr (A_KMAJOR) {
            #pragma unroll
            for (int i = 0; i < 2; ++i) {
                int o = tid + i * 256;
                int r = o >> 5, c = (o & 31) << 2;
                cpa16(&As.d[bf][r][c], &Ag[(size_t)(kt * 16 + r) * Astride + c]);
            }
        } else {
            #pragma unroll
            for (int i = 0; i < 2; ++i) {
                int o = tid + i * 256;
                int r = o >> 2, c = (o & 3) << 2;
                cpa16(&As.d[bf][r][c], &Ag[(size_t)r * Astride + kt * 16 + c]);
            }
        }
        if constexpr (B_KMAJOR) {
            #pragma unroll
            for (int i = 0; i < 2; ++i) {
                int o = tid + i * 256;
                int r = o >> 5, c = (o & 31) << 2;
                cpa16(&Bs.d[bf][r][c], &Bg[(size_t)(kt * 16 + r) * Bstride + c]);
            }
        } else {
            #pragma unroll
            for (int i = 0; i < 2; ++i) {
                int o = tid + i * 256;
                int r = o >> 2, c = (o & 3) << 2;
                cpa16(&Bs.d[bf][r][c], &Bg[(size_t)r * Bstride + kt * 16 + c]);
            }
        }
    };

    stage(0, 0);
    CP_COMMIT();
    CP_WAIT0();
    __syncthreads();

    for (int kt = 0; kt < nkt; ++kt) {
        int cur = kt & 1;
        if (kt + 1 < nkt) stage(kt + 1, cur ^ 1);
        CP_COMMIT();

        #pragma unroll
        for (int ks = 0; ks < 16; ks += 8) {
            int kr = ks + (lane & 3);
            unsigned afh[4][4], afl[4][4], bfh[4][2], bfl[4][2];
            #pragma unroll
            for (int mi = 0; mi < 4; ++mi) {
                int mr = wm * 64 + mi * 16 + (lane >> 2);
                float v0, v1, v2, v3;
                if constexpr (A_KMAJOR) {
                    v0 = As.d[cur][kr][mr];     v1 = As.d[cur][kr][mr + 8];
                    v2 = As.d[cur][kr + 4][mr]; v3 = As.d[cur][kr + 4][mr + 8];
                } else {
                    v0 = As.d[cur][mr][kr];     v1 = As.d[cur][mr + 8][kr];
                    v2 = As.d[cur][mr][kr + 4]; v3 = As.d[cur][mr + 8][kr + 4];
                }
                float h;
                h = f2tf_f(v0); afh[mi][0] = fu(h); afl[mi][0] = fu(v0 - h);
                h = f2tf_f(v1); afh[mi][1] = fu(h); afl[mi][1] = fu(v1 - h);
                h = f2tf_f(v2); afh[mi][2] = fu(h); afl[mi][2] = fu(v2 - h);
                h = f2tf_f(v3); afh[mi][3] = fu(h); afl[mi][3] = fu(v3 - h);
            }
            #pragma unroll
            for (int ni = 0; ni < 4; ++ni) {
                int nc = wn * 32 + ni * 8 + (lane >> 2);
                float v0, v1;
                if constexpr (B_KMAJOR) {
                    v0 = Bs.d[cur][kr][nc]; v1 = Bs.d[cur][kr + 4][nc];
                } else {
                    v0 = Bs.d[cur][nc][kr]; v1 = Bs.d[cur][nc][kr + 4];
                }
                float h;
                h = f2tf_f(v0); bfh[ni][0] = fu(h); bfl[ni][0] = fu(v0 - h);
                h = f2tf_f(v1); bfh[ni][1] = fu(h); bfl[ni][1] = fu(v1 - h);
            }
            #pragma unroll
            for (int mi = 0; mi < 4; ++mi)
                #pragma unroll
                for (int ni = 0; ni < 4; ++ni) {
                    mma8(acc[mi][ni], afl[mi], bfh[ni]);   // lo*hi
                    mma8(acc[mi][ni], afh[mi], bfl[ni]);   // hi*lo
                    mma8(acc[mi][ni], afh[mi], bfh[ni]);   // hi*hi
                }
        }

        CP_WAIT0();
        __syncthreads();
    }

    #pragma unroll
    for (int mi = 0; mi < 4; ++mi) {
        int r0 = m0 + wm * 64 + mi * 16 + (lane >> 2);
        #pragma unroll
        for (int ni = 0; ni < 4; ++ni) {
            int c0i = n0 + wn * 32 + ni * 8 + 2 * (lane & 3);
            float a0 = 0.f, a1 = 0.f, b0v = 0.f, b1v = 0.f;
            if (BIAS_MODE == 1) { a0 = bias[c0i]; a1 = bias[c0i + 1]; b0v = a0; b1v = a1; }
            if (BIAS_MODE == 2) { a0 = a1 = bias[r0]; b0v = b1v = bias[r0 + 8]; }
            float2 v0 = { acc[mi][ni][0] + a0, acc[mi][ni][1] + a1 };
            float2 v1 = { acc[mi][ni][2] + b0v, acc[mi][ni][3] + b1v };
            *(float2*)&Cg[(size_t)r0 * Cstride + c0i] = v0;
            *(float2*)&Cg[(size_t)(r0 + 8) * Cstride + c0i] = v1;
        }
    }
}

template<bool A_KMAJOR, bool B_KMAJOR, int BIAS_MODE>
__global__ void __launch_bounds__(256) gemm_tc(
    const float* __restrict__ A, const float* __restrict__ Bm,
    const float* __restrict__ bias, float* __restrict__ Cm,
    int K, int Astride, int Bstride, int Cstride,
    long sAb, long sBb, long sCb)
{
    __shared__ Tile<A_KMAJOR> As;
    __shared__ Tile<B_KMAJOR> Bs;
    int m0 = blockIdx.x * 128, n0 = blockIdx.y * 128;
    int b = blockIdx.z;
    const float* Ag = A + (size_t)b * sAb;
    const float* Bg = Bm + (size_t)b * sBb;
    float* Cg = Cm + (size_t)b * sCb;
    if (A_KMAJOR) Ag += m0; else Ag += (size_t)m0 * Astride;
    if (B_KMAJOR) Bg += n0; else Bg += (size_t)n0 * Bstride;
    gemm_body<A_KMAJOR, B_KMAJOR, BIAS_MODE>(
        Ag, Bg, bias, Cg, K, Astride, Bstride, Cstride, m0, n0, As, Bs);
}

// merged projection kernel (theta/g/phi), z = proj*8 + b
__global__ void __launch_bounds__(256) gemm_proj(
    const float* __restrict__ rgb_p, const float* __restrict__ ev_p,
    const float* __restrict__ tw, const float* __restrict__ tb,
    const float* __restrict__ gw, const float* __restrict__ gb,
    const float* __restrict__ pw, const float* __restrict__ pb,
    float* __restrict__ theta, float* __restrict__ gconv, float* __restrict__ pconv)
{
    __shared__ Tile<true> As;
    __shared__ Tile<false> Bs;
    int z = blockIdx.z;
    int pz = z >> 3, b = z & 7;
    const float* Aall = (pz == 0) ? rgb_p : ev_p;
    const float* Bw   = (pz == 0) ? tw : (pz == 1 ? gw : pw);
    const float* bias = (pz == 0) ? tb : (pz == 1 ? gb : pb);
    float* Cm         = (pz == 0) ? theta : (pz == 1 ? gconv : pconv);
    int m0 = blockIdx.x * 128;
    const float* Ag = Aall + (size_t)b * C_ * NQ_ + m0;   // k-major [256][4096]
    float* Cg = Cm + (size_t)b * NQ_ * IC_;
    gemm_body<true, false, 1>(Ag, Bw, bias, Cg, C_, NQ_, C_, IC_, m0, 0, As, Bs);
}

// ------------------------- 2x2 maxpool NCHW, vectorized (2 outputs/thread) -------------------------
__global__ void pool2_kernel(const float* __restrict__ in, float* __restrict__ out, int n) {
    int i = blockIdx.x * blockDim.x + threadIdx.x;
    if (i >= n) return;                      // n = B*C*64*32
    int ow2 = i & 31;
    int t  = i >> 5;
    int oh = t & 63;
    int bc = t >> 6;
    const float* p = in + ((size_t)bc * H_ + 2 * oh) * W_ + ow2 * 4;
    float4 a = *(const float4*)p;
    float4 c = *(const float4*)(p + W_);
    float2 r;
    r.x = fmaxf(fmaxf(a.x, a.y), fmaxf(c.x, c.y));
    r.y = fmaxf(fmaxf(a.z, a.w), fmaxf(c.z, c.w));
    *(float2*)&out[((size_t)bc * H2_ + oh) * W2_ + ow2 * 2] = r;
}

// ------------------------- row-pool [B][4096][128] -> [B][1024][128] -------------------------
__global__ void poolrows_kernel(const float* __restrict__ in, float* __restrict__ out, int n) {
    int i = blockIdx.x * blockDim.x + threadIdx.x;
    if (i >= n) return;                      // n = B*1024*32 (float4 units)
    int ic4 = i & 31;
    int kv  = (i >> 5) & 1023;
    int b   = i >> 15;
    int ph = kv >> 5, pw = kv & 31;
    int s00 = (ph * 2) * 64 + pw * 2;
    const float4* p = (const float4*)(in + ((size_t)b * NQ_ + s00) * IC_) + ic4;
    float4 a = p[0], c = p[32], d = p[64 * 32], e = p[65 * 32];
    float4 r;
    r.x = fmaxf(fmaxf(a.x, c.x), fmaxf(d.x, e.x));
    r.y = fmaxf(fmaxf(a.y, c.y), fmaxf(d.y, e.y));
    r.z = fmaxf(fmaxf(a.z, c.z), fmaxf(d.z, e.z));
    r.w = fmaxf(fmaxf(a.w, c.w), fmaxf(d.w, e.w));
    ((float4*)(out + ((size_t)b * NKV_ + kv) * IC_))[ic4] = r;
}

// ------------------------- warp-per-row softmax over 1024 -------------------------
__global__ void __launch_bounds__(256) softmax_kernel(float* __restrict__ S) {
    int warp = threadIdx.x >> 5, lane = threadIdx.x & 31;
    size_t row = (size_t)blockIdx.x * 8 + warp;
    float* p = S + row * NKV_ + lane * 4;
    float4 v[8];
    float mx = -INFINITY;
    #pragma unroll
    for (int j = 0; j < 8; ++j) {
        v[j] = *(const float4*)&p[j * 128];
        mx = fmaxf(mx, fmaxf(fmaxf(v[j].x, v[j].y), fmaxf(v[j].z, v[j].w)));
    }
    #pragma unroll
    for (int o = 16; o; o >>= 1) mx = fmaxf(mx, __shfl_xor_sync(0xffffffffu, mx, o));
    float s = 0.f;
    #pragma unroll
    for (int j = 0; j < 8; ++j) {
        v[j].x = __expf(v[j].x - mx);
        v[j].y = __expf(v[j].y - mx);
        v[j].z = __expf(v[j].z - mx);
        v[j].w = __expf(v[j].w - mx);
        s += (v[j].x + v[j].y) + (v[j].z + v[j].w);
    }
    #pragma unroll
    for (int o = 16; o; o >>= 1) s += __shfl_xor_sync(0xffffffffu, s, o);
    float inv = 1.f / s;
    #pragma unroll
    for (int j = 0; j < 8; ++j) {
        v[j].x *= inv; v[j].y *= inv; v[j].z *= inv; v[j].w *= inv;
        *(float4*)&p[j * 128] = v[j];
    }
}

// ------------------------- BatchNorm stats (deterministic, float4) -------------------------
__global__ void bnstats_kernel() {
    __shared__ float ss[256], ss2[256];
    int co = blockIdx.x, tid = threadIdx.x;
    float s = 0.f, s2 = 0.f;
    for (int i = tid; i < B_ * NQ_ / 4; i += 256) {
        int b = i >> 10, sp = (i & 1023) << 2;
        float4 v = *(const float4*)&d_wy[((size_t)b * C_ + co) * NQ_ + sp];
        s += (v.x + v.y) + (v.z + v.w);
        s2 += (v.x * v.x + v.y * v.y) + (v.z * v.z + v.w * v.w);
    }
    ss[tid] = s; ss2[tid] = s2;
    __syncthreads();
    for (int st = 128; st > 0; st >>= 1) {
        if (tid < st) { ss[tid] += ss[tid + st]; ss2[tid] += ss2[tid + st]; }
        __syncthreads();
    }
    if (tid == 0) {
        const float invN = 1.f / (B_ * NQ_);
        float mean = ss[0] * invN;
        float var  = ss2[0] * invN - mean * mean;
        d_mean[co] = mean;
        d_rstd[co] = rsqrtf(var + 1e-5f);
    }
}

// ------------------------- BN apply + residual + 2x upsample -------------------------
// One thread per source element-pair: reads wy/rgb once, writes 2 rows x float4.
__global__ void final_kernel(const float* __restrict__ gamma, const float* __restrict__ beta,
                             float* __restrict__ out, int n) {
    int i = blockIdx.x * blockDim.x + threadIdx.x;
    if (i >= n) return;                      // n = B*C*64*32
    int w2p = i & 31;                        // pair of pooled cols: 2*w2p, 2*w2p+1
    int h2  = (i >> 5) & 63;
    int co  = (i >> 11) & 255;
    int b   = i >> 19;
    size_t base = ((size_t)b * C_ + co) * NQ_ + h2 * W2_ + 2 * w2p;
    float mn = d_mean[co], rs = d_rstd[co], gm = gamma[co], bt = beta[co];
    float2 wyv = *(const float2*)&d_wy[base];
    float2 rgv = *(const float2*)&d_rgb_p[base];
    float va = (wyv.x - mn) * rs * gm + bt + rgv.x;
    float vb = (wyv.y - mn) * rs * gm + bt + rgv.y;
    float4 r = { va, va, vb, vb };
    size_t ob = (((size_t)b * C_ + co) * H_ + 2 * h2) * W_ + 4 * w2p;
    *(float4*)&out[ob]      = r;             // row 2*h2
    *(float4*)&out[ob + W_] = r;             // row 2*h2+1
}

// ------------------------- launch -------------------------
extern "C" void kernel_launch(void* const* d_in, const int* in_sizes, int n_in,
                              void* d_out, int out_size) {
    const float* rgb     = (const float*)d_in[0];
    const float* event_  = (const float*)d_in[1];
    const float* g_w     = (const float*)d_in[2];
    const float* g_b     = (const float*)d_in[3];
    const float* theta_w = (const float*)d_in[4];
    const float* theta_b = (const float*)d_in[5];
    const float* phi_w   = (const float*)d_in[6];
    const float* phi_b   = (const float*)d_in[7];
    const float* W_w     = (const float*)d_in[8];
    const float* W_b     = (const float*)d_in[9];
    const float* bn_g    = (const float*)d_in[10];
    const float* bn_b    = (const float*)d_in[11];
    float* out = (float*)d_out;

    float *rgb_p, *ev_p, *theta, *gconv, *pconv, *g, *phi, *S, *y, *wy;
    cudaGetSymbolAddress((void**)&rgb_p, d_rgb_p);
    cudaGetSymbolAddress((void**)&ev_p,  d_ev_p);
    cudaGetSymbolAddress((void**)&theta, d_theta);
    cudaGetSymbolAddress((void**)&gconv, d_gconv);
    cudaGetSymbolAddress((void**)&pconv, d_pconv);
    cudaGetSymbolAddress((void**)&g,     d_g);
    cudaGetSymbolAddress((void**)&phi,   d_phi);
    cudaGetSymbolAddress((void**)&S,     d_S);
    cudaGetSymbolAddress((void**)&y,     d_y);
    cudaGetSymbolAddress((void**)&wy,    d_wy);

    // 1) initial 2x2 maxpool on both modalities (2 outputs/thread)
    {
        int n = B_ * C_ * H2_ * W2_ / 2;
        pool2_kernel<<<(n + 255) / 256, 256>>>(rgb,    rgb_p, n);
        pool2_kernel<<<(n + 255) / 256, 256>>>(event_, ev_p,  n);
    }
    // 2) merged 1x1 conv projections (theta, g, phi) in one launch
    {
        dim3 grid(NQ_ / 128, 1, 24);
        gemm_proj<<<grid, 256>>>(rgb_p, ev_p, theta_w, theta_b, g_w, g_b,
                                 phi_w, phi_b, theta, gconv, pconv);
    }
    // 3) sub-sample pool for g and phi
    {
        int n = B_ * NKV_ * (IC_ / 4);
        poolrows_kernel<<<(n + 255) / 256, 256>>>(gconv, g,   n);
        poolrows_kernel<<<(n + 255) / 256, 256>>>(pconv, phi, n);
    }
    // 4a) scores: S[b][q][kv] = sum_c theta[b][q][c] phi[b][kv][c]
    {
        dim3 grid(NQ_ / 128, NKV_ / 128, B_);
        gemm_tc<false, false, 0><<<grid, 256>>>(theta, phi, nullptr, S,
            IC_, IC_, IC_, NKV_, (long)NQ_ * IC_, (long)NKV_ * IC_, (long)NQ_ * NKV_);
    }
    // 4b) softmax rows
    softmax_kernel<<<B_ * NQ_ / 8, 256>>>(S);
    // 4c) y[b][q][ic] = sum_kv P[b][q][kv] g[b][kv][ic]
    {
        dim3 grid(NQ_ / 128, 1, B_);
        gemm_tc<false, true, 0><<<grid, 256>>>(S, g, nullptr, y,
            NKV_, NKV_, IC_, IC_, (long)NQ_ * NKV_, (long)NKV_ * IC_, (long)NQ_ * IC_);
    }
    // 5) output conv: wy[b][co][s] = sum_ic W_w[co][ic] y[b][s][ic] + W_b[co]
    {
        dim3 grid(C_ / 128, NQ_ / 128, B_);
        gemm_tc<false, false, 2><<<grid, 256>>>(W_w, y, W_b, wy,
            IC_, IC_, IC_, NQ_, 0, (long)NQ_ * IC_, (long)C_ * NQ_);
    }
    // 6) BN stats
    bnstats_kernel<<<C_, 256>>>();
    // 7) BN apply + residual + 2x upsample
    {
        int n = B_ * C_ * H2_ * W2_ / 2;
        final_kernel<<<(n + 255) / 256, 256>>>(bn_g, bn_b, out, n);
    }
}